// round 3
// baseline (speedup 1.0000x reference)
#include <cuda_runtime.h>

// Problem constants
#define BB    512
#define SEQL  96
#define PREDL 48
#define TOTL  144          // SEQL + PREDL
#define CIN   7
#define DM    128
#define KSZ   5
#define PADL  2
#define G3    384          // 3*DM
#define WCONV (KSZ*DM*DM)  // 81920

// ---------------- device scratch (no allocations allowed) ----------------
__device__ float g_temb[BB * TOTL * DM];    // temporal embedding, full horizon
__device__ float g_xcat[BB * TOTL * CIN];   // x_enc ++ predictions
__device__ float g_emb [BB * SEQL * DM];    // value+temporal embedding window [b][t][d]
__device__ float g_c1  [BB * SEQL * DM];    // conv ping
__device__ float g_c2  [BB * SEQL * DM];    // conv pong
__device__ float g_gx  [BB * SEQL * G3];    // x @ Wi^T + bi
__device__ float g_wc  [3 * WCONV];         // conv weights packed [sel][k*DM+i][o]
__device__ float g_wvt [CIN * DM];          // W_val^T  [c][d]
__device__ float g_wit [DM * G3];           // Wi^T     [d][g]

// ---------------- one-time (per call) prep kernels ----------------

__global__ void pack_kernel(const float* __restrict__ w1, const float* __restrict__ w2,
                            const float* __restrict__ w3, const float* __restrict__ wval,
                            const float* __restrict__ wi) {
    int idx = blockIdx.x * 256 + threadIdx.x;
    if (idx < WCONV) {
        int r = idx / DM, o = idx - r * DM;
        int k = r / DM,  i = r - k * DM;
        int s = (o * DM + i) * KSZ + k;     // src layout [O][I][K]
        g_wc[idx]             = w1[s];
        g_wc[WCONV + idx]     = w2[s];
        g_wc[2 * WCONV + idx] = w3[s];
    }
    if (idx < DM * G3) {
        int d = idx / G3, g = idx - d * G3;
        g_wit[idx] = wi[g * DM + d];        // src [G3][DM]
    }
    if (idx < CIN * DM) {
        int c = idx / DM, d = idx - c * DM;
        g_wvt[idx] = wval[d * CIN + c];     // src [DM][CIN]
    }
}

__global__ void temb_kernel(const int* __restrict__ ymark,
                            const float* __restrict__ hour, const float* __restrict__ wk,
                            const float* __restrict__ day,  const float* __restrict__ mon) {
    int bl = blockIdx.x;          // b*TOTL + l
    int d  = threadIdx.x;
    const int* y = ymark + bl * 4;
    int i0 = y[0], i1 = y[1], i2 = y[2], i3 = y[3];
    g_temb[bl * DM + d] = hour[i0 * DM + d] + wk[i1 * DM + d]
                        + day [i2 * DM + d] + mon[i3 * DM + d];
}

__global__ void initx_kernel(const float* __restrict__ xenc) {
    int idx = blockIdx.x * 256 + threadIdx.x;
    if (idx >= BB * TOTL * CIN) return;
    int c = idx % CIN;
    int t = (idx / CIN) % TOTL;
    int b = idx / (CIN * TOTL);
    g_xcat[idx] = (t < SEQL) ? xenc[(b * SEQL + t) * CIN + c] : 0.f;
}

// ---------------- per-step kernels ----------------

// x_emb[b][t][d] = sum_c xcat[b][step+t][c] * Wval[d][c] + b_val[d] + temb[b][step+t][d]
__global__ void embed_kernel(const float* __restrict__ bval, int step) {
    int bl = blockIdx.x;                 // b*SEQL + t
    int b  = bl / SEQL, t = bl - b * SEQL;
    int d  = threadIdx.x;
    __shared__ float xs[CIN];
    if (d < CIN) xs[d] = g_xcat[(b * TOTL + step + t) * CIN + d];
    __syncthreads();
    float acc = bval[d] + g_temb[(b * TOTL + step + t) * DM + d];
#pragma unroll
    for (int c = 0; c < CIN; c++) acc = fmaf(xs[c], g_wvt[c * DM + d], acc);
    g_emb[bl * DM + d] = acc;
}

__device__ __forceinline__ float* bufptr(int s) {
    return s == 0 ? g_emb : (s == 1 ? g_c1 : g_c2);
}

// Conv1d(128->128,k=5,pad=2) + ReLU as implicit GEMM.
// Per block: batch b, C[96,128] = A[96,640] * Wp[640,128].
// A[t][r] = in[b][t + (r/128) - 2][r%128] (zero padded in t).
__global__ __launch_bounds__(256) void conv_kernel(int srcs, int dsts, int wsel,
                                                   const float* __restrict__ bias) {
    const float* __restrict__ in  = bufptr(srcs);
    float*       __restrict__ out = bufptr(dsts);
    const float* __restrict__ wp  = g_wc + wsel * WCONV;

    __shared__ float As[16][SEQL + 1];   // [kk][t], padded (96 % 32 == 0)
    __shared__ float Bs[16][DM];

    int tid = threadIdx.x;
    int tx = tid & 15, ty = tid >> 4;
    float acc[6][8];
#pragma unroll
    for (int m = 0; m < 6; m++)
#pragma unroll
        for (int n = 0; n < 8; n++) acc[m][n] = 0.f;

    const float* xb = in + (size_t)blockIdx.x * SEQL * DM;

    for (int kc = 0; kc < 40; kc++) {           // K = 640 in chunks of 16
        int k  = kc >> 3;                       // conv tap (chunk never crosses taps)
        int ib = (kc & 7) << 4;                 // input-channel base
#pragma unroll
        for (int q = 0; q < 6; q++) {           // 96*16 = 1536 elements
            int e = tid + 256 * q;
            int t = e >> 4, rr = e & 15;
            int ts = t + k - PADL;
            As[rr][t] = (ts >= 0 && ts < SEQL) ? xb[ts * DM + ib + rr] : 0.f;
        }
#pragma unroll
        for (int q = 0; q < 8; q++) {           // 16*128 = 2048 elements
            int e = tid + 256 * q;
            int rr = e >> 7, o = e & 127;
            Bs[rr][o] = wp[(kc * 16 + rr) * DM + o];
        }
        __syncthreads();
#pragma unroll
        for (int rr = 0; rr < 16; rr++) {
            float a[6], bv[8];
#pragma unroll
            for (int m = 0; m < 6; m++) a[m] = As[rr][ty + 16 * m];
#pragma unroll
            for (int n = 0; n < 8; n++) bv[n] = Bs[rr][tx + 16 * n];
#pragma unroll
            for (int m = 0; m < 6; m++)
#pragma unroll
                for (int n = 0; n < 8; n++) acc[m][n] = fmaf(a[m], bv[n], acc[m][n]);
        }
        __syncthreads();
    }
    float* ob = out + (size_t)blockIdx.x * SEQL * DM;
#pragma unroll
    for (int m = 0; m < 6; m++)
#pragma unroll
        for (int n = 0; n < 8; n++) {
            int t = ty + 16 * m, o = tx + 16 * n;
            float v = acc[m][n] + bias[o];
            ob[t * DM + o] = fmaxf(v, 0.f);
        }
}

// gx[b][t][g] = conv3_out[b][t][:] @ Wi^T + bi   (conv3 out lives in g_c1)
__global__ __launch_bounds__(256) void gx_kernel(const float* __restrict__ bi) {
    const float* __restrict__ in = g_c1;
    int b = blockIdx.x, ns = blockIdx.y;        // ns selects 128-wide slice of 384

    __shared__ float As[16][SEQL + 1];
    __shared__ float Bs[16][DM];

    int tid = threadIdx.x;
    int tx = tid & 15, ty = tid >> 4;
    float acc[6][8];
#pragma unroll
    for (int m = 0; m < 6; m++)
#pragma unroll
        for (int n = 0; n < 8; n++) acc[m][n] = 0.f;

    const float* xb = in + (size_t)b * SEQL * DM;
    for (int kc = 0; kc < 8; kc++) {            // K = 128
#pragma unroll
        for (int q = 0; q < 6; q++) {
            int e = tid + 256 * q;
            int t = e >> 4, rr = e & 15;
            As[rr][t] = xb[t * DM + kc * 16 + rr];
        }
#pragma unroll
        for (int q = 0; q < 8; q++) {
            int e = tid + 256 * q;
            int rr = e >> 7, o = e & 127;
            Bs[rr][o] = g_wit[(kc * 16 + rr) * G3 + ns * DM + o];
        }
        __syncthreads();
#pragma unroll
        for (int rr = 0; rr < 16; rr++) {
            float a[6], bv[8];
#pragma unroll
            for (int m = 0; m < 6; m++) a[m] = As[rr][ty + 16 * m];
#pragma unroll
            for (int n = 0; n < 8; n++) bv[n] = Bs[rr][tx + 16 * n];
#pragma unroll
            for (int m = 0; m < 6; m++)
#pragma unroll
                for (int n = 0; n < 8; n++) acc[m][n] = fmaf(a[m], bv[n], acc[m][n]);
        }
        __syncthreads();
    }
#pragma unroll
    for (int m = 0; m < 6; m++)
#pragma unroll
        for (int n = 0; n < 8; n++) {
            int t = ty + 16 * m, o = tx + 16 * n;
            g_gx[((size_t)b * SEQL + t) * G3 + ns * DM + o] = acc[m][n] + bi[ns * DM + o];
        }
}

// GRU over 96 timesteps for 4 batch rows per block; Wh row j in registers.
// Then fc -> prediction, written back into g_xcat (next window) and d_out.
__global__ __launch_bounds__(384, 1) void gru_kernel(const float* __restrict__ Wh,
        const float* __restrict__ bh, const float* __restrict__ fcw,
        const float* __restrict__ fcb, float* __restrict__ dout, int step) {
    int j  = threadIdx.x;            // gate row 0..383
    int b0 = blockIdx.x * 4;         // 4 batch rows per block

    float4 wr[32];
    {
        const float4* p = reinterpret_cast<const float4*>(Wh + j * DM);
#pragma unroll
        for (int q = 0; q < 32; q++) wr[q] = p[q];
    }
    float bhj = bh[j];

    __shared__ __align__(16) float h_s[4][DM];
    __shared__ float S1[4][G3];      // r,z: gx+gh+bh ; n-slot: gh+bh
    __shared__ float S2[4][DM];      // n-slot: gx
    for (int e = j; e < 4 * DM; e += 384) (&h_s[0][0])[e] = 0.f;
    __syncthreads();

    for (int t = 0; t < SEQL; t++) {
        float acc0 = 0.f, acc1 = 0.f, acc2 = 0.f, acc3 = 0.f;
#pragma unroll
        for (int q = 0; q < 32; q++) {
            float4 w  = wr[q];
            float4 a0 = reinterpret_cast<const float4*>(h_s[0])[q];
            float4 a1 = reinterpret_cast<const float4*>(h_s[1])[q];
            float4 a2 = reinterpret_cast<const float4*>(h_s[2])[q];
            float4 a3 = reinterpret_cast<const float4*>(h_s[3])[q];
            acc0 = fmaf(w.x, a0.x, fmaf(w.y, a0.y, fmaf(w.z, a0.z, fmaf(w.w, a0.w, acc0))));
            acc1 = fmaf(w.x, a1.x, fmaf(w.y, a1.y, fmaf(w.z, a1.z, fmaf(w.w, a1.w, acc1))));
            acc2 = fmaf(w.x, a2.x, fmaf(w.y, a2.y, fmaf(w.z, a2.z, fmaf(w.w, a2.w, acc2))));
            acc3 = fmaf(w.x, a3.x, fmaf(w.y, a3.y, fmaf(w.z, a3.z, fmaf(w.w, a3.w, acc3))));
        }
        float accs[4] = {acc0, acc1, acc2, acc3};
#pragma unroll
        for (int r = 0; r < 4; r++) {
            float gx = g_gx[(((size_t)(b0 + r)) * SEQL + t) * G3 + j];
            float gh = accs[r] + bhj;
            if (j < 2 * DM) S1[r][j] = gx + gh;
            else            { S1[r][j] = gh; S2[r][j - 2 * DM] = gx; }
        }
        __syncthreads();
        if (j < DM) {
#pragma unroll
            for (int r = 0; r < 4; r++) {
                float rg = 1.f / (1.f + expf(-S1[r][j]));
                float zg = 1.f / (1.f + expf(-S1[r][DM + j]));
                float ng = tanhf(S2[r][j] + rg * S1[r][2 * DM + j]);
                h_s[r][j] = (1.f - zg) * ng + zg * h_s[r][j];
            }
        }
        __syncthreads();
    }

    if (j < 4 * CIN) {
        int r = j / CIN, c = j - r * CIN;
        float acc = fcb[c];
        for (int d = 0; d < DM; d++) acc = fmaf(h_s[r][d], fcw[c * DM + d], acc);
        int b = b0 + r;
        g_xcat[((size_t)b * TOTL + SEQL + step) * CIN + c] = acc;
        dout[((size_t)b * PREDL + step) * CIN + c] = acc;
    }
}

// ---------------- launcher ----------------
extern "C" void kernel_launch(void* const* d_in, const int* in_sizes, int n_in,
                              void* d_out, int out_size) {
    (void)in_sizes; (void)n_in; (void)out_size;
    const float* x_enc   = (const float*)d_in[0];
    // d_in[1] = x_mark (unused by reference)
    const int*   y_mark  = (const int*)  d_in[2];
    const float* hour_e  = (const float*)d_in[3];
    const float* wk_e    = (const float*)d_in[4];
    const float* day_e   = (const float*)d_in[5];
    const float* mon_e   = (const float*)d_in[6];
    const float* W_val   = (const float*)d_in[7];
    const float* b_val   = (const float*)d_in[8];
    const float* c1w     = (const float*)d_in[9];
    const float* c1b     = (const float*)d_in[10];
    const float* c2w     = (const float*)d_in[11];
    const float* c2b     = (const float*)d_in[12];
    const float* c3w     = (const float*)d_in[13];
    const float* c3b     = (const float*)d_in[14];
    const float* gWi     = (const float*)d_in[15];
    const float* gWh     = (const float*)d_in[16];
    const float* gbi     = (const float*)d_in[17];
    const float* gbh     = (const float*)d_in[18];
    const float* fcw     = (const float*)d_in[19];
    const float* fcb     = (const float*)d_in[20];
    float* out = (float*)d_out;

    pack_kernel<<<(WCONV + 255) / 256, 256>>>(c1w, c2w, c3w, W_val, gWi);
    temb_kernel<<<BB * TOTL, DM>>>(y_mark, hour_e, wk_e, day_e, mon_e);
    initx_kernel<<<(BB * TOTL * CIN + 255) / 256, 256>>>(x_enc);

    for (int i = 0; i < PREDL; i++) {
        embed_kernel<<<BB * SEQL, DM>>>(b_val, i);
        conv_kernel<<<BB, 256>>>(0, 1, 0, c1b);   // g_emb -> g_c1
        conv_kernel<<<BB, 256>>>(1, 2, 1, c2b);   // g_c1  -> g_c2
        conv_kernel<<<BB, 256>>>(2, 1, 2, c3b);   // g_c2  -> g_c1
        gx_kernel<<<dim3(BB, 3), 256>>>(gbi);     // g_c1  -> g_gx
        gru_kernel<<<BB / 4, 384>>>(gWh, gbh, fcw, fcb, out, i);
    }
}

// round 4
// speedup vs baseline: 1.8264x; 1.8264x over previous
#include <cuda_runtime.h>

#define BB    512
#define SEQL  96
#define PREDL 48
#define TOTL  144
#define CIN   7
#define DM    128
#define G3    384
#define KSZ   5
#define PADL  2
#define WCONV (KSZ*DM*DM)   // 81920

// ---------------- device scratch (static, no allocations) ----------------
__device__ float g_temb[BB * TOTL * DM];
__device__ float g_xcat[BB * TOTL * CIN];
__device__ float g_emb [BB * TOTL * DM];     // absolute-timeline embedding
__device__ float g_c1  [BB * TOTL * DM];     // global conv stages (frontier-clipped)
__device__ float g_c2  [BB * TOTL * DM];
__device__ float g_c3  [BB * TOTL * DM];
__device__ float g_gx  [BB * TOTL * G3];     // global gx (113 MB)
__device__ float g_lb1 [BB * 10 * DM];       // per-step left-boundary scratch
__device__ float g_lb2 [BB * 8  * DM];
__device__ float g_lb3 [BB * 6  * DM];
__device__ float g_lbgx[BB * 6  * G3];
__device__ float g_wc  [3 * WCONV];          // conv weights packed [sel][k*DM+ic][o]
__device__ float g_wvt [CIN * DM];           // W_val^T
__device__ float g_wit [DM * G3];            // Wi^T

// selectors (host cannot take __device__ addresses directly)
__device__ __forceinline__ float* sel_buf(int s) {
    switch (s) {
        case 0: return g_emb;  case 1: return g_c1;  case 2: return g_c2;
        case 3: return g_c3;   case 4: return g_lb1; case 5: return g_lb2;
        case 6: return g_lb3;  case 7: return g_lbgx; default: return g_gx;
    }
}
__device__ __forceinline__ const float* sel_w(int s) {
    return (s < 3) ? (g_wc + s * WCONV) : g_wit;
}

// ---------------- prep kernels ----------------
__global__ void pack_kernel(const float* __restrict__ w1, const float* __restrict__ w2,
                            const float* __restrict__ w3, const float* __restrict__ wval,
                            const float* __restrict__ wi) {
    int idx = blockIdx.x * 256 + threadIdx.x;
    if (idx < WCONV) {
        int r = idx / DM, o = idx - r * DM;
        int k = r / DM,  i = r - k * DM;
        int s = (o * DM + i) * KSZ + k;
        g_wc[idx]             = w1[s];
        g_wc[WCONV + idx]     = w2[s];
        g_wc[2 * WCONV + idx] = w3[s];
    }
    if (idx < DM * G3) {
        int d = idx / G3, g = idx - d * G3;
        g_wit[idx] = wi[g * DM + d];
    }
    if (idx < CIN * DM) {
        int c = idx / DM, d = idx - c * DM;
        g_wvt[idx] = wval[d * CIN + c];
    }
}

__global__ void temb_kernel(const int* __restrict__ ymark,
                            const float* __restrict__ hour, const float* __restrict__ wk,
                            const float* __restrict__ day,  const float* __restrict__ mon) {
    int bl = blockIdx.x, d = threadIdx.x;
    const int* y = ymark + bl * 4;
    g_temb[bl * DM + d] = hour[y[0] * DM + d] + wk[y[1] * DM + d]
                        + day [y[2] * DM + d] + mon[y[3] * DM + d];
}

__global__ void initx_kernel(const float* __restrict__ xenc) {
    int idx = blockIdx.x * 256 + threadIdx.x;
    if (idx >= BB * TOTL * CIN) return;
    int c = idx % CIN;
    int t = (idx / CIN) % TOTL;
    int b = idx / (CIN * TOTL);
    g_xcat[idx] = (t < SEQL) ? xenc[(b * SEQL + t) * CIN + c] : 0.f;
}

// embedding for absolute positions [p0, p0+np)
__global__ void embed_kernel(const float* __restrict__ bval, int p0, int np) {
    int bl = blockIdx.x;
    int b = bl / np, pi = bl - b * np;
    int p = p0 + pi;
    int d = threadIdx.x;
    __shared__ float xs[CIN];
    if (d < CIN) xs[d] = g_xcat[(b * TOTL + p) * CIN + d];
    __syncthreads();
    float acc = bval[d] + g_temb[(b * TOTL + p) * DM + d];
#pragma unroll
    for (int c = 0; c < CIN; c++) acc = fmaf(xs[c], g_wvt[c * DM + d], acc);
    g_emb[(b * TOTL + p) * DM + d] = acc;
}

// ---------------- generic gather-GEMM (conv taps or pointwise) ----------------
// Rows (b, pi), b<512, pi<npos. A[row][kcol] = src[b][pbase+pi+(kcol>>7)-2][kcol&127]
// gathered with zero outside q in [qlo, qhi]. C = relu?(A*W + bias). Tile 32x128.
__global__ __launch_bounds__(256) void convgemm(
    int ssel, int srcBS, int pbase, int qlo, int qhi,
    int wsel, int Nw, const float* __restrict__ bias,
    int dsel, int dstBS, int dstPS, int dstPB,
    int npos, int KC, int relu)
{
    const float* __restrict__ src = sel_buf(ssel);
    const float* __restrict__ w   = sel_w(wsel);
    float*       __restrict__ dst = sel_buf(dsel);

    __shared__ float As[16][33];
    __shared__ float Bs[16][DM];

    int tid = threadIdx.x;
    int tx = tid & 15, ty = tid >> 4;
    int ncol0 = blockIdx.y * DM;

    // As-loader rows: r0 = ty, r1 = ty+16 ; kk = tx
    int R0 = blockIdx.x * 32 + ty;
    int R1 = R0 + 16;
    int b0 = R0 / npos, p0 = R0 - b0 * npos;
    int b1 = R1 / npos, p1 = R1 - b1 * npos;
    const float* s0 = src + (size_t)b0 * srcBS;
    const float* s1 = src + (size_t)b1 * srcBS;
    int pr0 = pbase + p0 - PADL;
    int pr1 = pbase + p1 - PADL;

    float acc[2][8];
#pragma unroll
    for (int m = 0; m < 2; m++)
#pragma unroll
        for (int n = 0; n < 8; n++) acc[m][n] = 0.f;

    for (int kc = 0; kc < KC; kc++) {
        int tap = kc >> 3;
        int icb = (kc & 7) << 4;
        int q0 = pr0 + tap, q1 = pr1 + tap;
        float v0 = (q0 >= qlo && q0 <= qhi) ? s0[(size_t)q0 * DM + icb + tx] : 0.f;
        float v1 = (q1 >= qlo && q1 <= qhi) ? s1[(size_t)q1 * DM + icb + tx] : 0.f;
        As[tx][ty]      = v0;
        As[tx][ty + 16] = v1;
#pragma unroll
        for (int qq = 0; qq < 8; qq++) {
            int e = tid + 256 * qq;
            int kk = e >> 7, o = e & 127;
            Bs[kk][o] = w[(size_t)(kc * 16 + kk) * Nw + ncol0 + o];
        }
        __syncthreads();
#pragma unroll
        for (int rr = 0; rr < 16; rr++) {
            float a0 = As[rr][ty], a1 = As[rr][ty + 16];
            float bv[8];
#pragma unroll
            for (int n = 0; n < 8; n++) bv[n] = Bs[rr][tx + 16 * n];
#pragma unroll
            for (int n = 0; n < 8; n++) {
                acc[0][n] = fmaf(a0, bv[n], acc[0][n]);
                acc[1][n] = fmaf(a1, bv[n], acc[1][n]);
            }
        }
        __syncthreads();
    }
    // writeback
#pragma unroll
    for (int m = 0; m < 2; m++) {
        int b = m ? b1 : b0;
        int pi = m ? p1 : p0;
        float* dp = dst + (size_t)b * dstBS + (size_t)(dstPB + pi) * dstPS + ncol0;
#pragma unroll
        for (int n = 0; n < 8; n++) {
            int o = tx + 16 * n;
            float v = acc[m][n] + bias[ncol0 + o];
            dp[o] = relu ? fmaxf(v, 0.f) : v;
        }
    }
}

// ---------------- GRU: 4 batch rows/block, Wh row in registers ----------------
__global__ __launch_bounds__(384, 1) void gru_kernel(const float* __restrict__ Wh,
        const float* __restrict__ bh, const float* __restrict__ fcw,
        const float* __restrict__ fcb, float* __restrict__ dout, int step) {
    int j  = threadIdx.x;
    int b0 = blockIdx.x * 4;

    float4 wr[32];
    {
        const float4* p = reinterpret_cast<const float4*>(Wh + j * DM);
#pragma unroll
        for (int q = 0; q < 32; q++) wr[q] = p[q];
    }
    float bhj = bh[j];

    __shared__ __align__(16) float h_s[4][DM];
    __shared__ float S1[4][G3];
    __shared__ float S2[4][DM];
    for (int e = j; e < 4 * DM; e += 384) (&h_s[0][0])[e] = 0.f;
    __syncthreads();

    for (int t = 0; t < SEQL; t++) {
        float acc0 = 0.f, acc1 = 0.f, acc2 = 0.f, acc3 = 0.f;
#pragma unroll
        for (int q = 0; q < 32; q++) {
            float4 w  = wr[q];
            float4 a0 = reinterpret_cast<const float4*>(h_s[0])[q];
            float4 a1 = reinterpret_cast<const float4*>(h_s[1])[q];
            float4 a2 = reinterpret_cast<const float4*>(h_s[2])[q];
            float4 a3 = reinterpret_cast<const float4*>(h_s[3])[q];
            acc0 = fmaf(w.x, a0.x, fmaf(w.y, a0.y, fmaf(w.z, a0.z, fmaf(w.w, a0.w, acc0))));
            acc1 = fmaf(w.x, a1.x, fmaf(w.y, a1.y, fmaf(w.z, a1.z, fmaf(w.w, a1.w, acc1))));
            acc2 = fmaf(w.x, a2.x, fmaf(w.y, a2.y, fmaf(w.z, a2.z, fmaf(w.w, a2.w, acc2))));
            acc3 = fmaf(w.x, a3.x, fmaf(w.y, a3.y, fmaf(w.z, a3.z, fmaf(w.w, a3.w, acc3))));
        }
        float accs[4] = {acc0, acc1, acc2, acc3};
#pragma unroll
        for (int r = 0; r < 4; r++) {
            int b = b0 + r;
            float gx = (t < 6)
                ? g_lbgx[((size_t)b * 6 + t) * G3 + j]
                : g_gx[((size_t)b * TOTL + step + t) * G3 + j];
            float gh = accs[r] + bhj;
            if (j < 2 * DM) S1[r][j] = gx + gh;
            else            { S1[r][j] = gh; S2[r][j - 2 * DM] = gx; }
        }
        __syncthreads();
        if (j < DM) {
#pragma unroll
            for (int r = 0; r < 4; r++) {
                float rg = 1.f / (1.f + expf(-S1[r][j]));
                float zg = 1.f / (1.f + expf(-S1[r][DM + j]));
                float ng = tanhf(S2[r][j] + rg * S1[r][2 * DM + j]);
                h_s[r][j] = (1.f - zg) * ng + zg * h_s[r][j];
            }
        }
        __syncthreads();
    }

    if (j < 4 * CIN) {
        int r = j / CIN, c = j - r * CIN;
        float acc = fcb[c];
        for (int d = 0; d < DM; d++) acc = fmaf(h_s[r][d], fcw[c * DM + d], acc);
        int b = b0 + r;
        g_xcat[((size_t)b * TOTL + SEQL + step) * CIN + c] = acc;
        dout[((size_t)b * PREDL + step) * CIN + c] = acc;
    }
}

// ---------------- launcher ----------------
extern "C" void kernel_launch(void* const* d_in, const int* in_sizes, int n_in,
                              void* d_out, int out_size) {
    (void)in_sizes; (void)n_in; (void)out_size;
    const float* x_enc  = (const float*)d_in[0];
    const int*   y_mark = (const int*)  d_in[2];
    const float* hour_e = (const float*)d_in[3];
    const float* wk_e   = (const float*)d_in[4];
    const float* day_e  = (const float*)d_in[5];
    const float* mon_e  = (const float*)d_in[6];
    const float* W_val  = (const float*)d_in[7];
    const float* b_val  = (const float*)d_in[8];
    const float* c1w    = (const float*)d_in[9];
    const float* c1b    = (const float*)d_in[10];
    const float* c2w    = (const float*)d_in[11];
    const float* c2b    = (const float*)d_in[12];
    const float* c3w    = (const float*)d_in[13];
    const float* c3b    = (const float*)d_in[14];
    const float* gWi    = (const float*)d_in[15];
    const float* gWh    = (const float*)d_in[16];
    const float* gbi    = (const float*)d_in[17];
    const float* gbh    = (const float*)d_in[18];
    const float* fcw    = (const float*)d_in[19];
    const float* fcb    = (const float*)d_in[20];
    float* out = (float*)d_out;

    const int SBS = TOTL * DM;      // batch stride of global 128-wide arrays
    const int GBS = TOTL * G3;      // batch stride of g_gx

    pack_kernel<<<(WCONV + 255) / 256, 256>>>(c1w, c2w, c3w, W_val, gWi);
    temb_kernel<<<BB * TOTL, DM>>>(y_mark, hour_e, wk_e, day_e, mon_e);
    initx_kernel<<<(BB * TOTL * CIN + 255) / 256, 256>>>(x_enc);
    embed_kernel<<<BB * SEQL, DM>>>(b_val, 0, SEQL);

    // initial full pass over p in [0,95] (left-clip 0, frontier 95)
    convgemm<<<1536, 256>>>(0, SBS, 0, 0, 95, 0, DM, c1b, 1, SBS, DM, 0, 96, 40, 1);
    convgemm<<<1536, 256>>>(1, SBS, 0, 0, 95, 1, DM, c2b, 2, SBS, DM, 0, 96, 40, 1);
    convgemm<<<1536, 256>>>(2, SBS, 0, 0, 95, 2, DM, c3b, 3, SBS, DM, 0, 96, 40, 1);
    convgemm<<<dim3(1536, 3), 256>>>(3, SBS, 2, 0, 95, 3, G3, gbi, 8, GBS, G3, 0, 96, 8, 0);

    for (int i = 0; i < PREDL; i++) {
        int F = 95 + i;  // data frontier (max valid emb position)
        if (i > 0) {
            // new embedding at p = 95+i (prediction appended by previous gru)
            embed_kernel<<<BB, DM>>>(b_val, F, 1);
            // incremental refresh with frontier clip
            convgemm<<<48,  256>>>(0, SBS, 93 + i, 0, F, 0, DM, c1b, 1, SBS, DM, 93 + i, 3, 40, 1);
            convgemm<<<80,  256>>>(1, SBS, 91 + i, 0, F, 1, DM, c2b, 2, SBS, DM, 91 + i, 5, 40, 1);
            convgemm<<<112, 256>>>(2, SBS, 89 + i, 0, F, 2, DM, c3b, 3, SBS, DM, 89 + i, 7, 40, 1);
            convgemm<<<dim3(112, 3), 256>>>(3, SBS, 91 + i, 0, F, 3, G3, gbi, 8, GBS, G3, 89 + i, 7, 8, 0);
        }
        // left-boundary cascade for window [i, i+96) (old data only)
        convgemm<<<160, 256>>>(0, SBS, i, i, i + 95, 0, DM, c1b, 4, 10 * DM, DM, 0, 10, 40, 1);
        convgemm<<<128, 256>>>(4, 10 * DM, 0, 0, 9, 1, DM, c2b, 5, 8 * DM, DM, 0, 8, 40, 1);
        convgemm<<<96,  256>>>(5, 8 * DM, 0, 0, 7, 2, DM, c3b, 6, 6 * DM, DM, 0, 6, 40, 1);
        convgemm<<<dim3(96, 3), 256>>>(6, 6 * DM, 2, 0, 5, 3, G3, gbi, 7, 6 * G3, G3, 0, 6, 8, 0);

        gru_kernel<<<BB / 4, 384>>>(gWh, gbh, fcw, fcb, out, i);
    }
}

// round 5
// speedup vs baseline: 2.6699x; 1.4619x over previous
#include <cuda_runtime.h>

#define BB    512
#define SEQL  96
#define PREDL 48
#define TOTL  144
#define CIN   7
#define DM    128
#define G3    384
#define KSZ   5
#define PADL  2
#define WCONV (KSZ*DM*DM)   // 81920

// ---------------- device scratch (static, no allocations) ----------------
__device__ float g_temb[BB * TOTL * DM];
__device__ float g_xcat[BB * TOTL * CIN];
__device__ float g_emb [BB * TOTL * DM];
__device__ float g_c1  [BB * TOTL * DM];
__device__ float g_c2  [BB * TOTL * DM];
__device__ float g_c3  [BB * TOTL * DM];
__device__ float g_gx  [BB * TOTL * G3];            // frontier-clipped global gx
__device__ float g_lbgx[(size_t)PREDL * BB * 6 * G3]; // all windows' left-boundary gx
__device__ float g_wc  [3 * WCONV];                 // conv w packed [sel][tap*128+ic][o]
__device__ float g_wvt [CIN * DM];
__device__ float g_wit [DM * G3];                   // Wi^T [d][g]

__device__ __forceinline__ float* sel_buf(int s) {
    switch (s) {
        case 0: return g_emb; case 1: return g_c1; case 2: return g_c2;
        case 3: return g_c3;  default: return g_gx;
    }
}
__device__ __forceinline__ const float* sel_w(int s) {
    return (s < 3) ? (g_wc + s * WCONV) : g_wit;
}

// ---------------- prep ----------------
__global__ void pack_kernel(const float* __restrict__ w1, const float* __restrict__ w2,
                            const float* __restrict__ w3, const float* __restrict__ wval,
                            const float* __restrict__ wi) {
    int idx = blockIdx.x * 256 + threadIdx.x;
    if (idx < WCONV) {
        int r = idx / DM, o = idx - r * DM;
        int k = r / DM,  i = r - k * DM;
        int s = (o * DM + i) * KSZ + k;
        g_wc[idx]             = w1[s];
        g_wc[WCONV + idx]     = w2[s];
        g_wc[2 * WCONV + idx] = w3[s];
    }
    if (idx < DM * G3) {
        int d = idx / G3, g = idx - d * G3;
        g_wit[idx] = wi[g * DM + d];
    }
    if (idx < CIN * DM) {
        int c = idx / DM, d = idx - c * DM;
        g_wvt[idx] = wval[d * CIN + c];
    }
}

__global__ void temb_kernel(const int* __restrict__ ymark,
                            const float* __restrict__ hour, const float* __restrict__ wk,
                            const float* __restrict__ day,  const float* __restrict__ mon) {
    int bl = blockIdx.x, d = threadIdx.x;
    const int* y = ymark + bl * 4;
    g_temb[bl * DM + d] = hour[y[0] * DM + d] + wk[y[1] * DM + d]
                        + day [y[2] * DM + d] + mon[y[3] * DM + d];
}

__global__ void initx_kernel(const float* __restrict__ xenc) {
    int idx = blockIdx.x * 256 + threadIdx.x;
    if (idx >= BB * TOTL * CIN) return;
    int c = idx % CIN;
    int t = (idx / CIN) % TOTL;
    int b = idx / (CIN * TOTL);
    g_xcat[idx] = (t < SEQL) ? xenc[(b * SEQL + t) * CIN + c] : 0.f;
}

__global__ void embed_kernel(const float* __restrict__ bval, int p0, int np) {
    int bl = blockIdx.x;
    int b = bl / np, pi = bl - b * np;
    int p = p0 + pi;
    int d = threadIdx.x;
    __shared__ float xs[CIN];
    if (d < CIN) xs[d] = g_xcat[(b * TOTL + p) * CIN + d];
    __syncthreads();
    float acc = bval[d] + g_temb[(b * TOTL + p) * DM + d];
#pragma unroll
    for (int c = 0; c < CIN; c++) acc = fmaf(xs[c], g_wvt[c * DM + d], acc);
    g_emb[(b * TOTL + p) * DM + d] = acc;
}

// ---------------- big tiled GEMM for the initial full pass ----------------
__global__ __launch_bounds__(256) void convgemm(
    int ssel, int srcBS, int pbase, int qlo, int qhi,
    int wsel, int Nw, const float* __restrict__ bias,
    int dsel, int dstBS, int dstPS, int dstPB,
    int npos, int KC, int relu)
{
    const float* __restrict__ src = sel_buf(ssel);
    const float* __restrict__ w   = sel_w(wsel);
    float*       __restrict__ dst = sel_buf(dsel);

    __shared__ float As[16][33];
    __shared__ float Bs[16][DM];

    int tid = threadIdx.x;
    int tx = tid & 15, ty = tid >> 4;
    int ncol0 = blockIdx.y * DM;

    int R0 = blockIdx.x * 32 + ty;
    int R1 = R0 + 16;
    int b0 = R0 / npos, p0 = R0 - b0 * npos;
    int b1 = R1 / npos, p1 = R1 - b1 * npos;
    const float* s0 = src + (size_t)b0 * srcBS;
    const float* s1 = src + (size_t)b1 * srcBS;
    int pr0 = pbase + p0 - PADL;
    int pr1 = pbase + p1 - PADL;

    float acc[2][8];
#pragma unroll
    for (int m = 0; m < 2; m++)
#pragma unroll
        for (int n = 0; n < 8; n++) acc[m][n] = 0.f;

    for (int kc = 0; kc < KC; kc++) {
        int tap = kc >> 3;
        int icb = (kc & 7) << 4;
        int q0 = pr0 + tap, q1 = pr1 + tap;
        float v0 = (q0 >= qlo && q0 <= qhi) ? s0[(size_t)q0 * DM + icb + tx] : 0.f;
        float v1 = (q1 >= qlo && q1 <= qhi) ? s1[(size_t)q1 * DM + icb + tx] : 0.f;
        As[tx][ty]      = v0;
        As[tx][ty + 16] = v1;
#pragma unroll
        for (int qq = 0; qq < 8; qq++) {
            int e = tid + 256 * qq;
            int kk = e >> 7, o = e & 127;
            Bs[kk][o] = w[(size_t)(kc * 16 + kk) * Nw + ncol0 + o];
        }
        __syncthreads();
#pragma unroll
        for (int rr = 0; rr < 16; rr++) {
            float a0 = As[rr][ty], a1 = As[rr][ty + 16];
            float bv[8];
#pragma unroll
            for (int n = 0; n < 8; n++) bv[n] = Bs[rr][tx + 16 * n];
#pragma unroll
            for (int n = 0; n < 8; n++) {
                acc[0][n] = fmaf(a0, bv[n], acc[0][n]);
                acc[1][n] = fmaf(a1, bv[n], acc[1][n]);
            }
        }
        __syncthreads();
    }
#pragma unroll
    for (int m = 0; m < 2; m++) {
        int b = m ? b1 : b0;
        int pi = m ? p1 : p0;
        float* dp = dst + (size_t)b * dstBS + (size_t)(dstPB + pi) * dstPS + ncol0;
#pragma unroll
        for (int n = 0; n < 8; n++) {
            int o = tx + 16 * n;
            float v = acc[m][n] + bias[ncol0 + o];
            dp[o] = relu ? fmaxf(v, 0.f) : v;
        }
    }
}

// ---------------- fused-stage helpers (256-thread blocks) ----------------
// acc[p] += sum_{tap,ic in g-half} w[(tap*128+ic)*128+o] * sA[(p+tap-OFF)*128+ic],
// skipping a = p+tap-OFF outside [0, NPOS+1] (compile-time per unrolled (p,tap)).
template<int NPOS, int OFF>
__device__ __forceinline__ void conv_stage_acc(const float* __restrict__ wp,
        const float* __restrict__ sA, int o, int g, float* acc) {
#pragma unroll
    for (int p = 0; p < NPOS; p++) acc[p] = 0.f;
    int icb = g * 64;
#pragma unroll
    for (int tap = 0; tap < 5; tap++) {
        const float* wt = wp + (size_t)(tap * 128) * 128 + o;
        for (int icx = 0; icx < 64; icx++) {
            float w = wt[(size_t)(icb + icx) * 128];
#pragma unroll
            for (int p = 0; p < NPOS; p++) {
                const int a = p + tap - OFF;
                if (a >= 0 && a <= NPOS + 1)
                    acc[p] = fmaf(w, sA[a * 128 + icb + icx], acc[p]);
            }
        }
    }
}

// combine the two k-halves, add bias (+relu), store to sN and optional global
template<int NPOS>
__device__ __forceinline__ void reduce_finalize(const float* acc, float* sRed, int o, int g,
        const float* __restrict__ bias, float* sN, float* gbase, int relu) {
    if (g == 1) {
#pragma unroll
        for (int p = 0; p < NPOS; p++) sRed[p * 128 + o] = acc[p];
    }
    __syncthreads();
    if (g == 0) {
#pragma unroll
        for (int p = 0; p < NPOS; p++) {
            float v = acc[p] + sRed[p * 128 + o] + bias[o];
            if (relu) v = fmaxf(v, 0.f);
            sN[p * 128 + o] = v;
            if (gbase) gbase[p * 128 + o] = v;
        }
    }
    __syncthreads();
}

// pointwise gx: dst[p][o] = sum_k sN3[p*128+k]*Wi^T[k][o] + gbi[o], o in [0,384)
template<int NP>
__device__ __forceinline__ void gx_stage(const float* __restrict__ sN3,
        const float* __restrict__ gbi, float* __restrict__ dst, int tid) {
#pragma unroll
    for (int pass = 0; pass < 2; pass++) {
        int o = (pass == 0) ? tid : 256 + tid;
        if (o < 384) {
            float acc[NP];
#pragma unroll
            for (int p = 0; p < NP; p++) acc[p] = 0.f;
            for (int k = 0; k < 128; k++) {
                float w = g_wit[(size_t)k * G3 + o];
#pragma unroll
                for (int p = 0; p < NP; p++) acc[p] = fmaf(w, sN3[p * 128 + k], acc[p]);
            }
#pragma unroll
            for (int p = 0; p < NP; p++) dst[(size_t)p * G3 + o] = acc[p] + gbi[o];
        }
    }
}

// ---------------- left-boundary precompute: all 48 windows, per-(b,win) block ----------------
__global__ __launch_bounds__(256) void lb_kernel(const float* __restrict__ c1b,
        const float* __restrict__ c2b, const float* __restrict__ c3b,
        const float* __restrict__ gbi) {
    int b = blockIdx.x, win = blockIdx.y;
    int tid = threadIdx.x, o = tid & 127, g = tid >> 7;
    __shared__ float sA[8 * 128];
    __shared__ float sN1[2 * 128], sN2[4 * 128], sN3[6 * 128];
    __shared__ float sRed[6 * 128];
    float acc[6];

    // lb1: wpos {0,1}; A = emb[win .. win+3]
    for (int e = tid; e < 4 * 128; e += 256) {
        int a = e >> 7, ic = e & 127;
        sA[e] = g_emb[((size_t)b * TOTL + win + a) * 128 + ic];
    }
    __syncthreads();
    conv_stage_acc<2, 2>(g_wc, sA, o, g, acc);
    reduce_finalize<2>(acc, sRed, o, g, c1b, sN1, nullptr, 1);

    // lb2: wpos [0,4); A a in [0,5]: a<2 new, else global c1[win+a] (final)
    for (int e = tid; e < 6 * 128; e += 256) {
        int a = e >> 7, ic = e & 127;
        sA[e] = (a < 2) ? sN1[a * 128 + ic]
                        : g_c1[((size_t)b * TOTL + win + a) * 128 + ic];
    }
    __syncthreads();
    conv_stage_acc<4, 2>(g_wc + WCONV, sA, o, g, acc);
    reduce_finalize<4>(acc, sRed, o, g, c2b, sN2, nullptr, 1);

    // lb3: wpos [0,6); A a in [0,7]: a<4 new, else global c2[win+a]
    for (int e = tid; e < 8 * 128; e += 256) {
        int a = e >> 7, ic = e & 127;
        sA[e] = (a < 4) ? sN2[a * 128 + ic]
                        : g_c2[((size_t)b * TOTL + win + a) * 128 + ic];
    }
    __syncthreads();
    conv_stage_acc<6, 2>(g_wc + 2 * WCONV, sA, o, g, acc);
    reduce_finalize<6>(acc, sRed, o, g, c3b, sN3, nullptr, 1);

    gx_stage<6>(sN3, gbi, g_lbgx + ((size_t)win * BB + b) * 6 * G3, tid);
}

// ---------------- fused per-step refresh: emb@F + c1(3) + c2(5) + c3(7) + gx(7) ----------------
__global__ __launch_bounds__(256) void refresh_kernel(const float* __restrict__ bval,
        const float* __restrict__ c1b, const float* __restrict__ c2b,
        const float* __restrict__ c3b, const float* __restrict__ gbi, int step) {
    int b = blockIdx.x;
    int F = SEQL - 1 + step;
    int tid = threadIdx.x, o = tid & 127, g = tid >> 7;
    __shared__ float sA[9 * 128];
    __shared__ float sN1[3 * 128], sN2[5 * 128], sN3[7 * 128];
    __shared__ float sRed[7 * 128];
    __shared__ float sEmb[128];
    float acc[7];

    // emb at F (prediction appended by previous gru)
    if (g == 0) {
        const float* xc = g_xcat + ((size_t)b * TOTL + F) * CIN;
        float a0 = bval[o] + g_temb[((size_t)b * TOTL + F) * 128 + o];
#pragma unroll
        for (int c = 0; c < CIN; c++) a0 = fmaf(xc[c], g_wvt[c * 128 + o], a0);
        sEmb[o] = a0;
        g_emb[((size_t)b * TOTL + F) * 128 + o] = a0;
    }
    __syncthreads();

    // c1 at [F-2,F]; A = emb[F-4..F] (a==4 new)
    for (int e = tid; e < 5 * 128; e += 256) {
        int a = e >> 7, ic = e & 127;
        sA[e] = (a < 4) ? g_emb[((size_t)b * TOTL + F - 4 + a) * 128 + ic] : sEmb[ic];
    }
    __syncthreads();
    conv_stage_acc<3, 0>(g_wc, sA, o, g, acc);
    reduce_finalize<3>(acc, sRed, o, g, c1b, sN1,
                       g_c1 + ((size_t)b * TOTL + F - 2) * 128, 1);

    // c2 at [F-4,F]; A = c1[F-6..F] (a>=4 new)
    for (int e = tid; e < 7 * 128; e += 256) {
        int a = e >> 7, ic = e & 127;
        sA[e] = (a < 4) ? g_c1[((size_t)b * TOTL + F - 6 + a) * 128 + ic]
                        : sN1[(a - 4) * 128 + ic];
    }
    __syncthreads();
    conv_stage_acc<5, 0>(g_wc + WCONV, sA, o, g, acc);
    reduce_finalize<5>(acc, sRed, o, g, c2b, sN2,
                       g_c2 + ((size_t)b * TOTL + F - 4) * 128, 1);

    // c3 at [F-6,F]; A = c2[F-8..F] (a>=4 new); nothing reads old c3 -> no global write
    for (int e = tid; e < 9 * 128; e += 256) {
        int a = e >> 7, ic = e & 127;
        sA[e] = (a < 4) ? g_c2[((size_t)b * TOTL + F - 8 + a) * 128 + ic]
                        : sN2[(a - 4) * 128 + ic];
    }
    __syncthreads();
    conv_stage_acc<7, 0>(g_wc + 2 * WCONV, sA, o, g, acc);
    reduce_finalize<7>(acc, sRed, o, g, c3b, sN3, nullptr, 1);

    gx_stage<7>(sN3, gbi, g_gx + ((size_t)b * TOTL + F - 6) * G3, tid);
}

// ---------------- GRU with packed fma.rn.f32x2 ----------------
__device__ __forceinline__ void ffma2(unsigned long long& acc,
                                      unsigned long long a, unsigned long long w) {
    asm("fma.rn.f32x2 %0, %1, %2, %0;" : "+l"(acc) : "l"(a), "l"(w));
}
__device__ __forceinline__ float sum2(unsigned long long v) {
    float2 f = *reinterpret_cast<float2*>(&v);
    return f.x + f.y;
}

__global__ __launch_bounds__(384, 1) void gru_kernel(const float* __restrict__ Wh,
        const float* __restrict__ bh, const float* __restrict__ fcw,
        const float* __restrict__ fcb, float* __restrict__ dout, int step) {
    int j  = threadIdx.x;
    int b0 = blockIdx.x * 4;

    ulonglong2 wr[32];
    {
        const ulonglong2* p = reinterpret_cast<const ulonglong2*>(Wh + (size_t)j * DM);
#pragma unroll
        for (int q = 0; q < 32; q++) wr[q] = p[q];
    }
    float bhj = bh[j];

    __shared__ __align__(16) float h_s[4][DM];
    __shared__ float S1[4][G3];
    __shared__ float S2[4][DM];
    for (int e = j; e < 4 * DM; e += 384) (&h_s[0][0])[e] = 0.f;
    __syncthreads();

    for (int t = 0; t < SEQL; t++) {
        unsigned long long c0 = 0, c1 = 0, c2 = 0, c3 = 0;
        const ulonglong2* h0 = reinterpret_cast<const ulonglong2*>(h_s[0]);
        const ulonglong2* h1 = reinterpret_cast<const ulonglong2*>(h_s[1]);
        const ulonglong2* h2 = reinterpret_cast<const ulonglong2*>(h_s[2]);
        const ulonglong2* h3 = reinterpret_cast<const ulonglong2*>(h_s[3]);
#pragma unroll
        for (int q = 0; q < 32; q++) {
            ulonglong2 w  = wr[q];
            ulonglong2 x0 = h0[q], x1 = h1[q], x2 = h2[q], x3 = h3[q];
            ffma2(c0, x0.x, w.x); ffma2(c0, x0.y, w.y);
            ffma2(c1, x1.x, w.x); ffma2(c1, x1.y, w.y);
            ffma2(c2, x2.x, w.x); ffma2(c2, x2.y, w.y);
            ffma2(c3, x3.x, w.x); ffma2(c3, x3.y, w.y);
        }
        float accs[4] = {sum2(c0), sum2(c1), sum2(c2), sum2(c3)};
#pragma unroll
        for (int r = 0; r < 4; r++) {
            int b = b0 + r;
            float gx = (t < 6)
                ? g_lbgx[(((size_t)step * BB + b) * 6 + t) * G3 + j]
                : g_gx[((size_t)b * TOTL + step + t) * G3 + j];
            float gh = accs[r] + bhj;
            if (j < 2 * DM) S1[r][j] = gx + gh;
            else            { S1[r][j] = gh; S2[r][j - 2 * DM] = gx; }
        }
        __syncthreads();
        if (j < DM) {
#pragma unroll
            for (int r = 0; r < 4; r++) {
                float rg = 1.f / (1.f + expf(-S1[r][j]));
                float zg = 1.f / (1.f + expf(-S1[r][DM + j]));
                float ng = tanhf(S2[r][j] + rg * S1[r][2 * DM + j]);
                h_s[r][j] = (1.f - zg) * ng + zg * h_s[r][j];
            }
        }
        __syncthreads();
    }

    if (j < 4 * CIN) {
        int r = j / CIN, c = j - r * CIN;
        float acc = fcb[c];
        for (int d = 0; d < DM; d++) acc = fmaf(h_s[r][d], fcw[c * DM + d], acc);
        int b = b0 + r;
        g_xcat[((size_t)b * TOTL + SEQL + step) * CIN + c] = acc;
        dout[((size_t)b * PREDL + step) * CIN + c] = acc;
    }
}

// ---------------- launcher ----------------
extern "C" void kernel_launch(void* const* d_in, const int* in_sizes, int n_in,
                              void* d_out, int out_size) {
    (void)in_sizes; (void)n_in; (void)out_size;
    const float* x_enc  = (const float*)d_in[0];
    const int*   y_mark = (const int*)  d_in[2];
    const float* hour_e = (const float*)d_in[3];
    const float* wk_e   = (const float*)d_in[4];
    const float* day_e  = (const float*)d_in[5];
    const float* mon_e  = (const float*)d_in[6];
    const float* W_val  = (const float*)d_in[7];
    const float* b_val  = (const float*)d_in[8];
    const float* c1w    = (const float*)d_in[9];
    const float* c1b    = (const float*)d_in[10];
    const float* c2w    = (const float*)d_in[11];
    const float* c2b    = (const float*)d_in[12];
    const float* c3w    = (const float*)d_in[13];
    const float* c3b    = (const float*)d_in[14];
    const float* gWi    = (const float*)d_in[15];
    const float* gWh    = (const float*)d_in[16];
    const float* gbi    = (const float*)d_in[17];
    const float* gbh    = (const float*)d_in[18];
    const float* fcw    = (const float*)d_in[19];
    const float* fcb    = (const float*)d_in[20];
    float* out = (float*)d_out;

    const int SBS = TOTL * DM;
    const int GBS = TOTL * G3;

    pack_kernel<<<(WCONV + 255) / 256, 256>>>(c1w, c2w, c3w, W_val, gWi);
    temb_kernel<<<BB * TOTL, DM>>>(y_mark, hour_e, wk_e, day_e, mon_e);
    initx_kernel<<<(BB * TOTL * CIN + 255) / 256, 256>>>(x_enc);
    embed_kernel<<<BB * SEQL, DM>>>(b_val, 0, SEQL);

    // initial full pass over p in [0,95] with frontier 95
    convgemm<<<1536, 256>>>(0, SBS, 0, 0, 95, 0, DM, c1b, 1, SBS, DM, 0, 96, 40, 1);
    convgemm<<<1536, 256>>>(1, SBS, 0, 0, 95, 1, DM, c2b, 2, SBS, DM, 0, 96, 40, 1);
    convgemm<<<1536, 256>>>(2, SBS, 0, 0, 95, 2, DM, c3b, 3, SBS, DM, 0, 96, 40, 1);
    convgemm<<<dim3(1536, 3), 256>>>(3, SBS, 2, 0, 95, 3, G3, gbi, 8, GBS, G3, 0, 96, 8, 0);

    // all 48 left-boundary cascades (depend only on initial data)
    lb_kernel<<<dim3(BB, PREDL), 256>>>(c1b, c2b, c3b, gbi);

    for (int i = 0; i < PREDL; i++) {
        if (i > 0)
            refresh_kernel<<<BB, 256>>>(b_val, c1b, c2b, c3b, gbi, i);
        gru_kernel<<<BB / 4, 384>>>(gWh, gbh, fcw, fcb, out, i);
    }
}

// round 6
// speedup vs baseline: 3.3031x; 1.2371x over previous
#include <cuda_runtime.h>

#define BB    512
#define SEQL  96
#define PREDL 48
#define TOTL  144
#define CIN   7
#define DM    128
#define G3    384
#define KSZ   5
#define PADL  2
#define NWIN  48
#define WCONV (KSZ*DM*DM)   // 81920

// ---------------- device scratch ----------------
__device__ float g_temb[BB * TOTL * DM];
__device__ float g_xcat[BB * TOTL * CIN];
__device__ float g_emb [BB * TOTL * DM];
__device__ float g_c1  [BB * TOTL * DM];
__device__ float g_c2  [BB * TOTL * DM];
__device__ float g_c3  [BB * TOTL * DM];
__device__ float g_gx  [BB * TOTL * G3];
__device__ float g_lbgx[(size_t)PREDL * BB * 6 * G3];
__device__ float g_lb1 [BB * NWIN * 2 * DM];
__device__ float g_lb2 [BB * NWIN * 4 * DM];
__device__ float g_lb3 [BB * NWIN * 6 * DM];
__device__ float g_wc  [3 * WCONV];          // [sel][tap*128+ic][o]
__device__ float g_wvt [CIN * DM];
__device__ float g_wit [DM * G3];            // Wi^T [d][g]

__device__ __forceinline__ float* sel_buf(int s) {
    switch (s) {
        case 0: return g_emb; case 1: return g_c1; case 2: return g_c2;
        case 3: return g_c3;  default: return g_gx;
    }
}
__device__ __forceinline__ const float* sel_w(int s) {
    return (s < 3) ? (g_wc + s * WCONV) : g_wit;
}

// ---------------- prep ----------------
__global__ void pack_kernel(const float* __restrict__ w1, const float* __restrict__ w2,
                            const float* __restrict__ w3, const float* __restrict__ wval,
                            const float* __restrict__ wi) {
    int idx = blockIdx.x * 256 + threadIdx.x;
    if (idx < WCONV) {
        int r = idx / DM, o = idx - r * DM;
        int k = r / DM,  i = r - k * DM;
        int s = (o * DM + i) * KSZ + k;
        g_wc[idx]             = w1[s];
        g_wc[WCONV + idx]     = w2[s];
        g_wc[2 * WCONV + idx] = w3[s];
    }
    if (idx < DM * G3) {
        int d = idx / G3, g = idx - d * G3;
        g_wit[idx] = wi[g * DM + d];
    }
    if (idx < CIN * DM) {
        int c = idx / DM, d = idx - c * DM;
        g_wvt[idx] = wval[d * CIN + c];
    }
}

__global__ void temb_kernel(const int* __restrict__ ymark,
                            const float* __restrict__ hour, const float* __restrict__ wk,
                            const float* __restrict__ day,  const float* __restrict__ mon) {
    int bl = blockIdx.x, d = threadIdx.x;
    const int* y = ymark + bl * 4;
    g_temb[bl * DM + d] = hour[y[0] * DM + d] + wk[y[1] * DM + d]
                        + day [y[2] * DM + d] + mon[y[3] * DM + d];
}

__global__ void initx_kernel(const float* __restrict__ xenc) {
    int idx = blockIdx.x * 256 + threadIdx.x;
    if (idx >= BB * TOTL * CIN) return;
    int c = idx % CIN;
    int t = (idx / CIN) % TOTL;
    int b = idx / (CIN * TOTL);
    g_xcat[idx] = (t < SEQL) ? xenc[(b * SEQL + t) * CIN + c] : 0.f;
}

__global__ void embed_kernel(const float* __restrict__ bval) {
    int bl = blockIdx.x;                       // b*SEQL + p
    int b = bl / SEQL, p = bl - b * SEQL;
    int d = threadIdx.x;
    __shared__ float xs[CIN];
    if (d < CIN) xs[d] = g_xcat[(b * TOTL + p) * CIN + d];
    __syncthreads();
    float acc = bval[d] + g_temb[(b * TOTL + p) * DM + d];
#pragma unroll
    for (int c = 0; c < CIN; c++) acc = fmaf(xs[c], g_wvt[c * DM + d], acc);
    g_emb[(b * TOTL + p) * DM + d] = acc;
}

// ---------------- tiled GEMM for the initial full pass ----------------
__global__ __launch_bounds__(256) void convgemm(
    int ssel, int srcBS, int pbase, int qlo, int qhi,
    int wsel, int Nw, const float* __restrict__ bias,
    int dsel, int dstBS, int dstPS, int dstPB,
    int npos, int KC, int relu)
{
    const float* __restrict__ src = sel_buf(ssel);
    const float* __restrict__ w   = sel_w(wsel);
    float*       __restrict__ dst = sel_buf(dsel);

    __shared__ float As[16][33];
    __shared__ float Bs[16][DM];

    int tid = threadIdx.x;
    int tx = tid & 15, ty = tid >> 4;
    int ncol0 = blockIdx.y * DM;

    int R0 = blockIdx.x * 32 + ty;
    int R1 = R0 + 16;
    int b0 = R0 / npos, p0 = R0 - b0 * npos;
    int b1 = R1 / npos, p1 = R1 - b1 * npos;
    const float* s0 = src + (size_t)b0 * srcBS;
    const float* s1 = src + (size_t)b1 * srcBS;
    int pr0 = pbase + p0 - PADL;
    int pr1 = pbase + p1 - PADL;

    float acc[2][8];
#pragma unroll
    for (int m = 0; m < 2; m++)
#pragma unroll
        for (int n = 0; n < 8; n++) acc[m][n] = 0.f;

    for (int kc = 0; kc < KC; kc++) {
        int tap = kc >> 3;
        int icb = (kc & 7) << 4;
        int q0 = pr0 + tap, q1 = pr1 + tap;
        float v0 = (q0 >= qlo && q0 <= qhi) ? s0[(size_t)q0 * DM + icb + tx] : 0.f;
        float v1 = (q1 >= qlo && q1 <= qhi) ? s1[(size_t)q1 * DM + icb + tx] : 0.f;
        As[tx][ty]      = v0;
        As[tx][ty + 16] = v1;
#pragma unroll
        for (int qq = 0; qq < 8; qq++) {
            int e = tid + 256 * qq;
            int kk = e >> 7, o = e & 127;
            Bs[kk][o] = w[(size_t)(kc * 16 + kk) * Nw + ncol0 + o];
        }
        __syncthreads();
#pragma unroll
        for (int rr = 0; rr < 16; rr++) {
            float a0 = As[rr][ty], a1 = As[rr][ty + 16];
            float bv[8];
#pragma unroll
            for (int n = 0; n < 8; n++) bv[n] = Bs[rr][tx + 16 * n];
#pragma unroll
            for (int n = 0; n < 8; n++) {
                acc[0][n] = fmaf(a0, bv[n], acc[0][n]);
                acc[1][n] = fmaf(a1, bv[n], acc[1][n]);
            }
        }
        __syncthreads();
    }
#pragma unroll
    for (int m = 0; m < 2; m++) {
        int b = m ? b1 : b0;
        int pi = m ? p1 : p0;
        float* dp = dst + (size_t)b * dstBS + (size_t)(dstPB + pi) * dstPS + ncol0;
#pragma unroll
        for (int n = 0; n < 8; n++) {
            int o = tx + 16 * n;
            float v = acc[m][n] + bias[ncol0 + o];
            dp[o] = relu ? fmaxf(v, 0.f) : v;
        }
    }
}

// ---------------- left-boundary cascades as 4 chip-wide GEMMs ----------------
// Rows R = (b*NWIN + win)*NPOS + p.  Stage ST gathers A with window-left zero clip.
template<int ST>
__device__ __forceinline__ float lb_fetch(int b, int win, int a, int ic) {
    if (ST == 0) return (a >= 0) ? g_emb[((size_t)b * TOTL + win + a) * DM + ic] : 0.f;
    if (ST == 1) {
        if (a < 0) return 0.f;
        return (a < 2) ? g_lb1[(((size_t)b * NWIN + win) * 2 + a) * DM + ic]
                       : g_c1[((size_t)b * TOTL + win + a) * DM + ic];
    }
    // ST == 2
    if (a < 0) return 0.f;
    return (a < 4) ? g_lb2[(((size_t)b * NWIN + win) * 4 + a) * DM + ic]
                   : g_c2[((size_t)b * TOTL + win + a) * DM + ic];
}

template<int ST>
__global__ __launch_bounds__(256) void lbgemm(const float* __restrict__ bias) {
    constexpr int NPOS = (ST == 0) ? 2 : (ST == 1) ? 4 : 6;   // ST==3 uses 6 too
    constexpr int KC   = (ST == 3) ? 8 : 40;
    constexpr int NW   = (ST == 3) ? G3 : DM;

    __shared__ float As[16][33];
    __shared__ float Bs[16][DM];

    int tid = threadIdx.x;
    int tx = tid & 15, ty = tid >> 4;
    int ncol0 = blockIdx.y * DM;
    const float* __restrict__ w = (ST == 3) ? g_wit : (g_wc + ST * WCONV);

    int R0 = blockIdx.x * 32 + ty, R1 = R0 + 16;
    int p0 = R0 % NPOS, wb0 = R0 / NPOS, win0 = wb0 % NWIN, b0 = wb0 / NWIN;
    int p1 = R1 % NPOS, wb1 = R1 / NPOS, win1 = wb1 % NWIN, b1 = wb1 / NWIN;

    float acc[2][8];
#pragma unroll
    for (int m = 0; m < 2; m++)
#pragma unroll
        for (int n = 0; n < 8; n++) acc[m][n] = 0.f;

    for (int kc = 0; kc < KC; kc++) {
        int tap = kc >> 3;
        int ic  = ((kc & 7) << 4) + tx;
        float v0, v1;
        if (ST == 3) {
            v0 = g_lb3[(((size_t)b0 * NWIN + win0) * 6 + p0) * DM + ic];
            v1 = g_lb3[(((size_t)b1 * NWIN + win1) * 6 + p1) * DM + ic];
        } else {
            v0 = lb_fetch<ST>(b0, win0, p0 + tap - PADL, ic);
            v1 = lb_fetch<ST>(b1, win1, p1 + tap - PADL, ic);
        }
        As[tx][ty]      = v0;
        As[tx][ty + 16] = v1;
#pragma unroll
        for (int qq = 0; qq < 8; qq++) {
            int e = tid + 256 * qq;
            int kk = e >> 7, o = e & 127;
            Bs[kk][o] = w[(size_t)(kc * 16 + kk) * NW + ncol0 + o];
        }
        __syncthreads();
#pragma unroll
        for (int rr = 0; rr < 16; rr++) {
            float a0 = As[rr][ty], a1 = As[rr][ty + 16];
            float bv[8];
#pragma unroll
            for (int n = 0; n < 8; n++) bv[n] = Bs[rr][tx + 16 * n];
#pragma unroll
            for (int n = 0; n < 8; n++) {
                acc[0][n] = fmaf(a0, bv[n], acc[0][n]);
                acc[1][n] = fmaf(a1, bv[n], acc[1][n]);
            }
        }
        __syncthreads();
    }
#pragma unroll
    for (int m = 0; m < 2; m++) {
        int b = m ? b1 : b0, win = m ? win1 : win0, p = m ? p1 : p0;
#pragma unroll
        for (int n = 0; n < 8; n++) {
            int o = tx + 16 * n;
            float v = acc[m][n] + bias[ncol0 + o];
            if (ST == 0) g_lb1[(((size_t)b * NWIN + win) * 2 + p) * DM + o] = fmaxf(v, 0.f);
            if (ST == 1) g_lb2[(((size_t)b * NWIN + win) * 4 + p) * DM + o] = fmaxf(v, 0.f);
            if (ST == 2) g_lb3[(((size_t)b * NWIN + win) * 6 + p) * DM + o] = fmaxf(v, 0.f);
            if (ST == 3) g_lbgx[(((size_t)win * BB + b) * 6 + p) * G3 + ncol0 + o] = v;
        }
    }
}

// ---------------- prologue conv stage (inside merged kernel) ----------------
// positions F-(NPOS-1)+p for p<NPOS; input a = p+tap over src base F-(NPOS+1);
// skip a > NPOS+1 (beyond frontier). 4 batch rows at once, 3-way k-split.
template<int NPOS>
__device__ __forceinline__ void prolog_stage(int b0, int F,
        const float* __restrict__ src, const float* __restrict__ wp,
        const float* __restrict__ bias, float* __restrict__ dst,
        float* sA4, float* sRedA, float* sRedB,
        int tid, int o, int g, int ic0, int ic1) {
    constexpr int NR = NPOS + 2;
    for (int e = tid; e < 4 * NR * DM; e += 384) {
        int ic = e & 127, ra = e >> 7;
        int r = ra / NR, a = ra - r * NR;
        sA4[e] = src[((size_t)(b0 + r) * TOTL + F - (NR - 1) + a) * DM + ic];
    }
    __syncthreads();
    float acc[NPOS][4];
#pragma unroll
    for (int p = 0; p < NPOS; p++)
#pragma unroll
        for (int r = 0; r < 4; r++) acc[p][r] = 0.f;
    for (int ic = ic0; ic < ic1; ic++) {
        float xv[4][NR];
#pragma unroll
        for (int r = 0; r < 4; r++)
#pragma unroll
            for (int a = 0; a < NR; a++) xv[r][a] = sA4[(r * NR + a) * DM + ic];
#pragma unroll
        for (int tap = 0; tap < 5; tap++) {
            float w = wp[(size_t)(tap * DM + ic) * DM + o];
#pragma unroll
            for (int p = 0; p < NPOS; p++) {
                const int a = p + tap;
                if (a <= NPOS + 1) {
#pragma unroll
                    for (int r = 0; r < 4; r++)
                        acc[p][r] = fmaf(w, xv[r][a], acc[p][r]);
                }
            }
        }
    }
    for (int r = 0; r < 4; r++) {
        if (g == 1) {
#pragma unroll
            for (int p = 0; p < NPOS; p++) sRedA[p * DM + o] = acc[p][r];
        } else if (g == 2) {
#pragma unroll
            for (int p = 0; p < NPOS; p++) sRedB[p * DM + o] = acc[p][r];
        }
        __syncthreads();
        if (g == 0) {
#pragma unroll
            for (int p = 0; p < NPOS; p++) {
                float v = acc[p][r] + sRedA[p * DM + o] + sRedB[p * DM + o] + bias[o];
                dst[((size_t)(b0 + r) * TOTL + F - (NPOS - 1) + p) * DM + o] = fmaxf(v, 0.f);
            }
        }
        __syncthreads();
    }
}

// ---------------- merged per-step kernel: refresh prologue + GRU t-loop ----------------
__device__ __forceinline__ void ffma2(unsigned long long& acc,
                                      unsigned long long a, unsigned long long w) {
    asm("fma.rn.f32x2 %0, %1, %2, %0;" : "+l"(acc) : "l"(a), "l"(w));
}
__device__ __forceinline__ float sum2(unsigned long long v) {
    float2 f = *reinterpret_cast<float2*>(&v);
    return f.x + f.y;
}

__global__ __launch_bounds__(384, 1) void gru_step(const float* __restrict__ Wh,
        const float* __restrict__ bh, const float* __restrict__ fcw,
        const float* __restrict__ fcb, const float* __restrict__ bval,
        const float* __restrict__ c1b, const float* __restrict__ c2b,
        const float* __restrict__ c3b, const float* __restrict__ gbi,
        float* __restrict__ dout, int step) {
    int tid = threadIdx.x;
    int b0  = blockIdx.x * 4;

    __shared__ __align__(16) float h_s[4][DM];
    __shared__ float S1[4][G3];
    __shared__ float S2[4][DM];
    __shared__ float sA4[4 * 9 * DM];
    __shared__ float sRedA[7 * DM];
    __shared__ float sRedB[7 * DM];

    if (step > 0) {
        const int F  = SEQL - 1 + step;
        const int o  = tid & 127;
        const int g  = tid >> 7;
        const int ic0 = (g == 0) ? 0 : (g == 1) ? 43 : 86;
        const int ic1 = (g == 0) ? 43 : (g == 1) ? 86 : 128;

        // embedding at frontier F for the block's 4 rows
        for (int e = tid; e < 4 * DM; e += 384) {
            int r = e >> 7, d = e & 127;
            int b = b0 + r;
            const float* xc = g_xcat + ((size_t)b * TOTL + F) * CIN;
            float a = bval[d] + g_temb[((size_t)b * TOTL + F) * DM + d];
#pragma unroll
            for (int c = 0; c < CIN; c++) a = fmaf(xc[c], g_wvt[c * DM + d], a);
            g_emb[((size_t)b * TOTL + F) * DM + d] = a;
        }
        __syncthreads();

        prolog_stage<3>(b0, F, g_emb, g_wc,             c1b, g_c1, sA4, sRedA, sRedB, tid, o, g, ic0, ic1);
        prolog_stage<5>(b0, F, g_c1,  g_wc + WCONV,     c2b, g_c2, sA4, sRedA, sRedB, tid, o, g, ic0, ic1);
        prolog_stage<7>(b0, F, g_c2,  g_wc + 2 * WCONV, c3b, g_c3, sA4, sRedA, sRedB, tid, o, g, ic0, ic1);

        // gx at F-6..F: rows split 4-way, cols in float4 quads
        for (int e = tid; e < 4 * 7 * DM; e += 384) {
            int ic = e & 127, rp = e >> 7;
            int r = rp / 7, p = rp - r * 7;
            sA4[e] = g_c3[((size_t)(b0 + r) * TOTL + F - 6 + p) * DM + ic];
        }
        __syncthreads();
        {
            int rq = tid / 96, cq = tid - rq * 96;
            float acc[7][4];
#pragma unroll
            for (int p = 0; p < 7; p++)
#pragma unroll
                for (int c = 0; c < 4; c++) acc[p][c] = 0.f;
            const float4* wv = reinterpret_cast<const float4*>(g_wit) + cq;
            const float* xb = sA4 + rq * 7 * DM;
            for (int k = 0; k < DM; k++) {
                float4 w = wv[(size_t)k * 96];
                float x[7];
#pragma unroll
                for (int p = 0; p < 7; p++) x[p] = xb[p * DM + k];
#pragma unroll
                for (int p = 0; p < 7; p++) {
                    acc[p][0] = fmaf(w.x, x[p], acc[p][0]);
                    acc[p][1] = fmaf(w.y, x[p], acc[p][1]);
                    acc[p][2] = fmaf(w.z, x[p], acc[p][2]);
                    acc[p][3] = fmaf(w.w, x[p], acc[p][3]);
                }
            }
            float4 bo = reinterpret_cast<const float4*>(gbi)[cq];
#pragma unroll
            for (int p = 0; p < 7; p++) {
                float4 v;
                v.x = acc[p][0] + bo.x; v.y = acc[p][1] + bo.y;
                v.z = acc[p][2] + bo.z; v.w = acc[p][3] + bo.w;
                *reinterpret_cast<float4*>(
                    g_gx + ((size_t)(b0 + rq) * TOTL + F - 6 + p) * G3 + cq * 4) = v;
            }
        }
        __syncthreads();
    }

    // ---- GRU t-loop ----
    int j = tid;
    ulonglong2 wr[32];
    {
        const ulonglong2* p = reinterpret_cast<const ulonglong2*>(Wh + (size_t)j * DM);
#pragma unroll
        for (int q = 0; q < 32; q++) wr[q] = p[q];
    }
    float bhj = bh[j];

    for (int e = j; e < 4 * DM; e += 384) (&h_s[0][0])[e] = 0.f;
    __syncthreads();

    for (int t = 0; t < SEQL; t++) {
        // prefetch gx (independent of h)
        float gxv[4];
#pragma unroll
        for (int r = 0; r < 4; r++) {
            int b = b0 + r;
            gxv[r] = (t < 6)
                ? g_lbgx[(((size_t)step * BB + b) * 6 + t) * G3 + j]
                : g_gx[((size_t)b * TOTL + step + t) * G3 + j];
        }
        unsigned long long c0 = 0, c1 = 0, c2 = 0, c3 = 0;
        const ulonglong2* h0 = reinterpret_cast<const ulonglong2*>(h_s[0]);
        const ulonglong2* h1 = reinterpret_cast<const ulonglong2*>(h_s[1]);
        const ulonglong2* h2 = reinterpret_cast<const ulonglong2*>(h_s[2]);
        const ulonglong2* h3 = reinterpret_cast<const ulonglong2*>(h_s[3]);
#pragma unroll
        for (int q = 0; q < 32; q++) {
            ulonglong2 w  = wr[q];
            ulonglong2 x0 = h0[q], x1 = h1[q], x2 = h2[q], x3 = h3[q];
            ffma2(c0, x0.x, w.x); ffma2(c0, x0.y, w.y);
            ffma2(c1, x1.x, w.x); ffma2(c1, x1.y, w.y);
            ffma2(c2, x2.x, w.x); ffma2(c2, x2.y, w.y);
            ffma2(c3, x3.x, w.x); ffma2(c3, x3.y, w.y);
        }
        float accs[4] = {sum2(c0), sum2(c1), sum2(c2), sum2(c3)};
#pragma unroll
        for (int r = 0; r < 4; r++) {
            float gh = accs[r] + bhj;
            if (j < 2 * DM) S1[r][j] = gxv[r] + gh;
            else            { S1[r][j] = gh; S2[r][j - 2 * DM] = gxv[r]; }
        }
        __syncthreads();
        // gate phase distributed over all warps (512 items / 384 threads)
        for (int e = j; e < 4 * DM; e += 384) {
            int r = e >> 7, d = e & 127;
            float rg = __fdividef(1.f, 1.f + __expf(-S1[r][d]));
            float zg = __fdividef(1.f, 1.f + __expf(-S1[r][DM + d]));
            float na = S2[r][d] + rg * S1[r][2 * DM + d];
            float ng = 1.f - __fdividef(2.f, __expf(2.f * na) + 1.f);
            h_s[r][d] = (1.f - zg) * ng + zg * h_s[r][d];
        }
        __syncthreads();
    }

    if (j < 4 * CIN) {
        int r = j / CIN, c = j - r * CIN;
        float acc = fcb[c];
        for (int d = 0; d < DM; d++) acc = fmaf(h_s[r][d], fcw[c * DM + d], acc);
        int b = b0 + r;
        g_xcat[((size_t)b * TOTL + SEQL + step) * CIN + c] = acc;
        dout[((size_t)b * PREDL + step) * CIN + c] = acc;
    }
}

// ---------------- launcher ----------------
extern "C" void kernel_launch(void* const* d_in, const int* in_sizes, int n_in,
                              void* d_out, int out_size) {
    (void)in_sizes; (void)n_in; (void)out_size;
    const float* x_enc  = (const float*)d_in[0];
    const int*   y_mark = (const int*)  d_in[2];
    const float* hour_e = (const float*)d_in[3];
    const float* wk_e   = (const float*)d_in[4];
    const float* day_e  = (const float*)d_in[5];
    const float* mon_e  = (const float*)d_in[6];
    const float* W_val  = (const float*)d_in[7];
    const float* b_val  = (const float*)d_in[8];
    const float* c1w    = (const float*)d_in[9];
    const float* c1b    = (const float*)d_in[10];
    const float* c2w    = (const float*)d_in[11];
    const float* c2b    = (const float*)d_in[12];
    const float* c3w    = (const float*)d_in[13];
    const float* c3b    = (const float*)d_in[14];
    const float* gWi    = (const float*)d_in[15];
    const float* gWh    = (const float*)d_in[16];
    const float* gbi    = (const float*)d_in[17];
    const float* gbh    = (const float*)d_in[18];
    const float* fcw    = (const float*)d_in[19];
    const float* fcb    = (const float*)d_in[20];
    float* out = (float*)d_out;

    const int SBS = TOTL * DM;
    const int GBS = TOTL * G3;

    pack_kernel<<<(WCONV + 255) / 256, 256>>>(c1w, c2w, c3w, W_val, gWi);
    temb_kernel<<<BB * TOTL, DM>>>(y_mark, hour_e, wk_e, day_e, mon_e);
    initx_kernel<<<(BB * TOTL * CIN + 255) / 256, 256>>>(x_enc);
    embed_kernel<<<BB * SEQL, DM>>>(b_val);

    // initial full pass over positions [0,95]
    convgemm<<<1536, 256>>>(0, SBS, 0, 0, 95, 0, DM, c1b, 1, SBS, DM, 0, 96, 40, 1);
    convgemm<<<1536, 256>>>(1, SBS, 0, 0, 95, 1, DM, c2b, 2, SBS, DM, 0, 96, 40, 1);
    convgemm<<<1536, 256>>>(2, SBS, 0, 0, 95, 2, DM, c3b, 3, SBS, DM, 0, 96, 40, 1);
    convgemm<<<dim3(1536, 3), 256>>>(3, SBS, 2, 0, 95, 3, G3, gbi, 8, GBS, G3, 0, 96, 8, 0);

    // left-boundary cascades for all 48 windows, as 4 chip-wide GEMMs
    lbgemm<0><<<1536, 256>>>(c1b);             // 49152 rows
    lbgemm<1><<<3072, 256>>>(c2b);             // 98304 rows
    lbgemm<2><<<4608, 256>>>(c3b);             // 147456 rows
    lbgemm<3><<<dim3(4608, 3), 256>>>(gbi);    // gx, N=384

    for (int i = 0; i < PREDL; i++)
        gru_step<<<BB / 4, 384>>>(gWh, gbh, fcw, fcb, b_val, c1b, c2b, c3b, gbi, out, i);
}